// round 1
// baseline (speedup 1.0000x reference)
#include <cuda_runtime.h>
#include <cstdint>

// Problem constants
#define NP 21504   // priors per image
#define KC 1024    // top-k
#define BB 64      // batch
#define NT 512     // threads per block
#define WORDS 32   // KC/32 mask words

// Shared memory layout (bytes)
#define SM_A      0        // 131072: scores float[NP] (86016) aliased with supmat u32[KC*32]
#define SM_KEYS   131072   // 8192: u64[KC]
#define SM_BX1    139264   // 4096
#define SM_BY1    143360
#define SM_BX2    147456
#define SM_BY2    151552
#define SM_AREA   155648
#define SM_ROWANY 159744   // 1024 u8
#define SM_KEEP   160768   // 1024 u8
#define SM_HIST   161792   // 1024: u32[256]
#define SM_SCAN   162816   // 1024: u32[256]
#define SM_MISC   163840   // misc: counter/chosen/above/remaining + u64 prefix
#define SM_TOTAL  164096

__global__ __launch_bounds__(NT, 1)
void facedet_kernel(const float* __restrict__ locs,
                    const float* __restrict__ confs,
                    const float* __restrict__ priors,
                    float* __restrict__ out, int out_size)
{
    extern __shared__ unsigned char sm[];
    float*              s_scores = (float*)(sm + SM_A);
    unsigned int*       s_sup    = (unsigned int*)(sm + SM_A);
    unsigned long long* s_keys   = (unsigned long long*)(sm + SM_KEYS);
    float*              s_x1     = (float*)(sm + SM_BX1);
    float*              s_y1     = (float*)(sm + SM_BY1);
    float*              s_x2     = (float*)(sm + SM_BX2);
    float*              s_y2     = (float*)(sm + SM_BY2);
    float*              s_area   = (float*)(sm + SM_AREA);
    unsigned char*      s_rowany = (unsigned char*)(sm + SM_ROWANY);
    unsigned char*      s_keep   = (unsigned char*)(sm + SM_KEEP);
    unsigned int*       s_hist   = (unsigned int*)(sm + SM_HIST);
    unsigned int*       s_scan   = (unsigned int*)(sm + SM_SCAN);
    int*                s_misc   = (int*)(sm + SM_MISC);
    unsigned long long* s_pref   = (unsigned long long*)(sm + SM_MISC + 16);

    const int b = blockIdx.x;
    const int tid = threadIdx.x;

    // -------- Phase 1: softmax scores (exact XLA sequence) --------
    const float* conf = confs + (size_t)b * NP * 2;
    for (int n = tid; n < NP; n += NT) {
        float2 c = __ldg((const float2*)(conf + 2 * n));
        float m  = fmaxf(c.x, c.y);
        float e0 = expf(__fsub_rn(c.x, m));
        float e1 = expf(__fsub_rn(c.y, m));
        s_scores[n] = __fdiv_rn(e1, __fadd_rn(e0, e1));
    }
    if (tid == 0) { s_misc[3] = KC; *s_pref = 0ULL; }
    __syncthreads();

    // -------- Phase 2: radix select K-th largest 64-bit key --------
    // key = (score_bits << 32) | ~idx  -> unique, (score desc, idx asc) order
    for (int shift = 56; shift >= 0; shift -= 8) {
        unsigned long long pref = *s_pref;
        int rem = s_misc[3];
        for (int i = tid; i < 256; i += NT) s_hist[i] = 0;
        __syncthreads();
        for (int n = tid; n < NP; n += NT) {
            unsigned long long key =
                ((unsigned long long)__float_as_uint(s_scores[n]) << 32) |
                (unsigned int)(~n);
            bool match = (shift == 56) ||
                         ((key >> (shift + 8)) == (pref >> (shift + 8)));
            if (match)
                atomicAdd(&s_hist[(unsigned int)(key >> shift) & 255u], 1u);
        }
        __syncthreads();
        if (tid < 256) s_scan[tid] = s_hist[tid];
        __syncthreads();
        // suffix sums over 256 bins
        for (int off = 1; off < 256; off <<= 1) {
            unsigned int v = 0;
            if (tid < 256) {
                v = s_scan[tid];
                if (tid + off < 256) v += s_scan[tid + off];
            }
            __syncthreads();
            if (tid < 256) s_scan[tid] = v;
            __syncthreads();
        }
        if (tid < 256) {
            unsigned int sb  = s_scan[tid];
            unsigned int sb1 = (tid < 255) ? s_scan[tid + 1] : 0u;
            if (sb >= (unsigned int)rem && sb1 < (unsigned int)rem) {
                s_misc[1] = tid;          // chosen byte
                s_misc[2] = (int)sb1;     // count strictly above chosen byte
            }
        }
        __syncthreads();
        if (tid == 0) {
            *s_pref = pref | ((unsigned long long)(unsigned int)s_misc[1] << shift);
            s_misc[3] = rem - s_misc[2];
        }
        __syncthreads();
    }
    const unsigned long long T = *s_pref;  // exact K-th largest key
    if (tid == 0) s_misc[0] = 0;
    __syncthreads();

    // -------- Phase 3: collect exactly KC keys >= T --------
    for (int n = tid; n < NP; n += NT) {
        unsigned long long key =
            ((unsigned long long)__float_as_uint(s_scores[n]) << 32) |
            (unsigned int)(~n);
        if (key >= T) {
            int p = atomicAdd(&s_misc[0], 1);
            if (p < KC) s_keys[p] = key;
        }
    }
    __syncthreads();

    // -------- Phase 4: bitonic sort KC keys descending --------
    for (int k = 2; k <= KC; k <<= 1) {
        for (int j = k >> 1; j > 0; j >>= 1) {
            for (int i = tid; i < KC; i += NT) {
                int ixj = i ^ j;
                if (ixj > i) {
                    unsigned long long a = s_keys[i];
                    unsigned long long c = s_keys[ixj];
                    bool desc = ((i & k) == 0);
                    if (desc ? (a < c) : (a > c)) {
                        s_keys[i] = c; s_keys[ixj] = a;
                    }
                }
            }
            __syncthreads();
        }
    }

    // -------- Phase 5: decode boxes (match XLA: no FMA contraction) --------
    const float* loc = locs + (size_t)b * NP * 4;
    for (int t = tid; t < KC; t += NT) {
        unsigned long long key = s_keys[t];
        int idx = (int)(~(unsigned int)key);
        float4 l = __ldg((const float4*)(loc + 4 * (size_t)idx));
        float4 p = __ldg((const float4*)(priors + 4 * (size_t)idx));
        float cx = __fadd_rn(p.x, __fmul_rn(__fmul_rn(l.x, 0.1f), p.z));
        float cy = __fadd_rn(p.y, __fmul_rn(__fmul_rn(l.y, 0.1f), p.w));
        float w  = __fmul_rn(p.z, expf(__fmul_rn(l.z, 0.2f)));
        float h  = __fmul_rn(p.w, expf(__fmul_rn(l.w, 0.2f)));
        float x1 = __fsub_rn(cx, __fdiv_rn(w, 2.0f));
        float y1 = __fsub_rn(cy, __fdiv_rn(h, 2.0f));
        float x2 = __fadd_rn(x1, w);
        float y2 = __fadd_rn(y1, h);
        s_x1[t] = x1; s_y1[t] = y1; s_x2[t] = x2; s_y2[t] = y2;
        float aw = fmaxf(__fsub_rn(x2, x1), 0.0f);
        float ah = fmaxf(__fsub_rn(y2, y1), 0.0f);
        s_area[t] = __fmul_rn(aw, ah);
    }
    __syncthreads();  // scores region is dead -> safe to overwrite with supmat

    // -------- Phase 6: suppression bitmatrix (upper triangular) --------
    for (int task = tid; task < KC * WORDS; task += NT) {
        int i  = task >> 5;
        int w  = task & 31;
        int j0 = w << 5;
        unsigned int m = 0;
        if (j0 + 31 > i) {
            float xi1 = s_x1[i], yi1 = s_y1[i];
            float xi2 = s_x2[i], yi2 = s_y2[i];
            float ai  = s_area[i];
            #pragma unroll 8
            for (int jj = 0; jj < 32; jj++) {
                int j = j0 + jj;
                if (j <= i) continue;
                float lx = fmaxf(xi1, s_x1[j]);
                float ly = fmaxf(yi1, s_y1[j]);
                float rx = fminf(xi2, s_x2[j]);
                float ry = fminf(yi2, s_y2[j]);
                float ww = fmaxf(__fsub_rn(rx, lx), 0.0f);
                float hh = fmaxf(__fsub_rn(ry, ly), 0.0f);
                float inter = __fmul_rn(ww, hh);
                float uni = __fsub_rn(__fadd_rn(ai, s_area[j]), inter);
                float iou = __fdiv_rn(inter, fmaxf(uni, 1e-9f));
                if (iou > 0.4f) m |= (1u << jj);
            }
        }
        s_sup[task] = m;
    }
    __syncthreads();
    for (int i = tid; i < KC; i += NT) {
        unsigned int any = 0;
        #pragma unroll
        for (int w = 0; w < WORDS; w++) any |= s_sup[i * WORDS + w];
        s_rowany[i] = any ? 1 : 0;
    }
    __syncthreads();

    // -------- Phase 7: sequential greedy scan (one warp) --------
    if (tid < 32) {
        unsigned int remv = 0;     // lane holds mask word `lane`
        const int lane = tid;
        for (int i = 0; i < KC; i++) {
            unsigned int rm = __shfl_sync(0xffffffffu, remv, i >> 5);
            float sc = __uint_as_float((unsigned int)(s_keys[i] >> 32));
            bool kept = !((rm >> (i & 31)) & 1u) && (sc > 0.5f);
            if (kept && s_rowany[i]) remv |= s_sup[i * WORDS + lane];
            if (lane == 0) s_keep[i] = kept ? (unsigned char)1 : (unsigned char)0;
        }
    }
    __syncthreads();

    // -------- Phase 8: write outputs --------
    // dets: [B, KC, 5] floats, then keep: [B, KC] as 0/1 floats
    const bool write_keep = (out_size >= BB * KC * 6);
    for (int t = tid; t < KC; t += NT) {
        float kf = s_keep[t] ? 1.0f : 0.0f;
        float sc = __uint_as_float((unsigned int)(s_keys[t] >> 32));
        size_t base = ((size_t)b * KC + t) * 5;
        out[base + 0] = __fmul_rn(s_x1[t], kf);
        out[base + 1] = __fmul_rn(s_y1[t], kf);
        out[base + 2] = __fmul_rn(s_x2[t], kf);
        out[base + 3] = __fmul_rn(s_y2[t], kf);
        out[base + 4] = __fmul_rn(sc, kf);
        if (write_keep)
            out[(size_t)BB * KC * 5 + (size_t)b * KC + t] = kf;
    }
}

extern "C" void kernel_launch(void* const* d_in, const int* in_sizes, int n_in,
                              void* d_out, int out_size)
{
    (void)in_sizes; (void)n_in;
    cudaFuncSetAttribute(facedet_kernel,
                         cudaFuncAttributeMaxDynamicSharedMemorySize, SM_TOTAL);
    facedet_kernel<<<BB, NT, SM_TOTAL>>>(
        (const float*)d_in[0],   // locs  [B, NP, 4]
        (const float*)d_in[1],   // confs [B, NP, 2]
        (const float*)d_in[2],   // priors [NP, 4]
        (float*)d_out, out_size);
}

// round 2
// speedup vs baseline: 4.8883x; 4.8883x over previous
#include <cuda_runtime.h>
#include <cstdint>

// Problem constants
#define NP 21504   // priors per image (512*42)
#define KC 1024    // top-k
#define BB 64      // batch
#define NT 512     // threads per block
#define WORDS 32   // KC/32 mask words
#define CCAP 2048  // candidate buffer (>= KC + ties)

// Shared memory layout (bytes)
#define SM_A      0        // 131072: scores float[NP] aliased with supmat u32[KC*32]
#define SM_KEYS   131072   // 16384: u64[2048]
#define SM_BX1    147456   // 4096
#define SM_BY1    151552
#define SM_BX2    155648
#define SM_BY2    159744
#define SM_AREA   163840
#define SM_ROWANY 167936   // 1024 u8
#define SM_HIST   168960   // 1024: u32[256]
#define SM_SCAN   169984   // 1024: u32[256]
#define SM_VALW   171008   // 128: u32[32] validity bits
#define SM_KEEPW  171136   // 128: u32[32] keep bits
#define SM_MISC   171264   // counters
#define SM_TOTAL  171392

__global__ __launch_bounds__(NT, 1)
void facedet_kernel(const float* __restrict__ locs,
                    const float* __restrict__ confs,
                    const float* __restrict__ priors,
                    float* __restrict__ out, int out_size)
{
    extern __shared__ unsigned char sm[];
    float*              s_scores = (float*)(sm + SM_A);
    unsigned int*       s_sup    = (unsigned int*)(sm + SM_A);
    unsigned long long* s_keys   = (unsigned long long*)(sm + SM_KEYS);
    float*              s_x1     = (float*)(sm + SM_BX1);
    float*              s_y1     = (float*)(sm + SM_BY1);
    float*              s_x2     = (float*)(sm + SM_BX2);
    float*              s_y2     = (float*)(sm + SM_BY2);
    float*              s_area   = (float*)(sm + SM_AREA);
    unsigned char*      s_rowany = (unsigned char*)(sm + SM_ROWANY);
    unsigned int*       s_hist   = (unsigned int*)(sm + SM_HIST);
    unsigned int*       s_scan   = (unsigned int*)(sm + SM_SCAN);
    unsigned int*       s_validw = (unsigned int*)(sm + SM_VALW);
    unsigned int*       s_keepw  = (unsigned int*)(sm + SM_KEEPW);
    int*                s_misc   = (int*)(sm + SM_MISC);

    const int b    = blockIdx.x;
    const int tid  = threadIdx.x;
    const int lane = tid & 31;
    const unsigned FULL = 0xffffffffu;

    // -------- Phase 1: softmax scores (exact XLA sequence) --------
    const float* conf = confs + (size_t)b * NP * 2;
    for (int n = tid; n < NP; n += NT) {
        float2 c = __ldg((const float2*)(conf + 2 * n));
        float m  = fmaxf(c.x, c.y);
        float e0 = expf(__fsub_rn(c.x, m));
        float e1 = expf(__fsub_rn(c.y, m));
        s_scores[n] = __fdiv_rn(e1, __fadd_rn(e0, e1));
    }
    if (tid == 0) { s_misc[3] = KC; s_misc[4] = 0; }  // rem, prefix
    __syncthreads();

    // -------- Phase 2: radix select K-th largest 32-bit score --------
    // 4 passes of 8 bits, match_any-aggregated smem histogram.
    #pragma unroll
    for (int shift = 24; shift >= 0; shift -= 8) {
        const unsigned int pref = (unsigned int)s_misc[4];
        const int rem = s_misc[3];
        for (int i = tid; i < 256; i += NT) s_hist[i] = 0;
        __syncthreads();
        for (int n = tid; n < NP; n += NT) {
            unsigned int sb = __float_as_uint(s_scores[n]);
            bool valid = (shift == 24) ||
                         ((sb >> (shift + 8)) == (pref >> (shift + 8)));
            unsigned int digit = (sb >> shift) & 255u;
            unsigned int mkey  = valid ? digit : 0xFFFFFFFFu;
            unsigned int mmask = __match_any_sync(FULL, mkey);
            if (valid) {
                int leader = __ffs(mmask) - 1;
                if (lane == leader) atomicAdd(&s_hist[digit], __popc(mmask));
            }
        }
        __syncthreads();
        if (tid < 256) s_scan[tid] = s_hist[tid];
        __syncthreads();
        // suffix sums over 256 bins
        for (int off = 1; off < 256; off <<= 1) {
            unsigned int v = 0;
            if (tid < 256) {
                v = s_scan[tid];
                if (tid + off < 256) v += s_scan[tid + off];
            }
            __syncthreads();
            if (tid < 256) s_scan[tid] = v;
            __syncthreads();
        }
        if (tid < 256) {
            unsigned int sb  = s_scan[tid];
            unsigned int sb1 = (tid < 255) ? s_scan[tid + 1] : 0u;
            if (sb >= (unsigned int)rem && sb1 < (unsigned int)rem) {
                s_misc[1] = tid;
                s_misc[2] = (int)sb1;
            }
        }
        __syncthreads();
        if (tid == 0) {
            s_misc[4] = (int)((unsigned int)s_misc[4] |
                              ((unsigned int)s_misc[1] << shift));
            s_misc[3] = s_misc[3] - s_misc[2];
        }
        __syncthreads();
    }
    const unsigned int Ts = (unsigned int)s_misc[4];  // K-th largest score bits
    if (tid == 0) s_misc[0] = 0;
    // zero candidate buffer (pad keys sort to bottom)
    for (int i = tid; i < CCAP; i += NT) s_keys[i] = 0ULL;
    __syncthreads();

    // -------- Phase 3: collect all keys with score >= Ts (warp-aggregated) ----
    for (int n = tid; n < NP; n += NT) {
        unsigned int sb = __float_as_uint(s_scores[n]);
        bool c = (sb >= Ts);
        unsigned int bal = __ballot_sync(FULL, c);
        if (bal) {
            int leader = __ffs(bal) - 1;
            int base = 0;
            if (lane == leader) base = atomicAdd(&s_misc[0], __popc(bal));
            base = __shfl_sync(FULL, base, leader);
            if (c) {
                int p = base + __popc(bal & ((1u << lane) - 1u));
                if (p < CCAP)
                    s_keys[p] = ((unsigned long long)sb << 32) |
                                (unsigned int)(~n);
            }
        }
    }
    __syncthreads();

    // -------- Phase 4: bitonic sort CCAP keys descending --------
    for (int k = 2; k <= CCAP; k <<= 1) {
        for (int j = k >> 1; j > 0; j >>= 1) {
            for (int i = tid; i < CCAP; i += NT) {
                int ixj = i ^ j;
                if (ixj > i) {
                    unsigned long long a = s_keys[i];
                    unsigned long long c = s_keys[ixj];
                    bool desc = ((i & k) == 0);
                    if (desc ? (a < c) : (a > c)) {
                        s_keys[i] = c; s_keys[ixj] = a;
                    }
                }
            }
            __syncthreads();
        }
    }
    // keys[0..KC) = exact sorted top-K (score desc, idx asc)

    // -------- Phase 5: decode boxes (match XLA: no FMA contraction) --------
    const float* loc = locs + (size_t)b * NP * 4;
    for (int t = tid; t < KC; t += NT) {
        unsigned long long key = s_keys[t];
        int idx = (int)(~(unsigned int)key);
        float4 l = __ldg((const float4*)(loc + 4 * (size_t)idx));
        float4 p = __ldg((const float4*)(priors + 4 * (size_t)idx));
        float cx = __fadd_rn(p.x, __fmul_rn(__fmul_rn(l.x, 0.1f), p.z));
        float cy = __fadd_rn(p.y, __fmul_rn(__fmul_rn(l.y, 0.1f), p.w));
        float w  = __fmul_rn(p.z, expf(__fmul_rn(l.z, 0.2f)));
        float h  = __fmul_rn(p.w, expf(__fmul_rn(l.w, 0.2f)));
        float x1 = __fsub_rn(cx, __fdiv_rn(w, 2.0f));
        float y1 = __fsub_rn(cy, __fdiv_rn(h, 2.0f));
        float x2 = __fadd_rn(x1, w);
        float y2 = __fadd_rn(y1, h);
        s_x1[t] = x1; s_y1[t] = y1; s_x2[t] = x2; s_y2[t] = y2;
        float aw = fmaxf(__fsub_rn(x2, x1), 0.0f);
        float ah = fmaxf(__fsub_rn(y2, y1), 0.0f);
        s_area[t] = __fmul_rn(aw, ah);
    }
    for (int i = tid; i < KC; i += NT) s_rowany[i] = 0;
    // validity bitmask (score > 0.5)
    for (int r = tid; r < KC; r += NT) {
        float sc = __uint_as_float((unsigned int)(s_keys[r] >> 32));
        unsigned int bal = __ballot_sync(FULL, sc > 0.5f);
        if (lane == 0) s_validw[r >> 5] = bal;
    }
    __syncthreads();  // scores region dead -> supmat may overwrite

    // -------- Phase 6: suppression bitmatrix (lanes = rows, j uniform) ------
    for (int t = tid; t < KC * WORDS; t += NT) {
        int w  = t >> 10;        // word (uniform within warp)
        int i  = t & 1023;       // row (consecutive across lanes)
        int j0 = w << 5;
        unsigned int m = 0;
        if (j0 + 31 > i) {
            float xi1 = s_x1[i], yi1 = s_y1[i];
            float xi2 = s_x2[i], yi2 = s_y2[i];
            float ai  = s_area[i];
            #pragma unroll 4
            for (int jj = 0; jj < 32; jj++) {
                int j = j0 + jj;     // warp-uniform -> broadcast LDS
                if (j <= i) continue;
                float lx = fmaxf(xi1, s_x1[j]);
                float ly = fmaxf(yi1, s_y1[j]);
                float rx = fminf(xi2, s_x2[j]);
                float ry = fminf(yi2, s_y2[j]);
                float ww = fmaxf(__fsub_rn(rx, lx), 0.0f);
                float hh = fmaxf(__fsub_rn(ry, ly), 0.0f);
                float inter = __fmul_rn(ww, hh);
                float um = fmaxf(__fsub_rn(__fadd_rn(ai, s_area[j]), inter),
                                 1e-9f);
                float t4 = __fmul_rn(0.4f, um);
                bool hi = inter > __fmul_rn(t4, 1.00002f);
                bool lo = inter < __fmul_rn(t4, 0.99998f);
                bool sup = hi;
                if (!hi && !lo)   // rare: within rounding band -> exact
                    sup = (__fdiv_rn(inter, um) > 0.4f);
                if (sup) m |= (1u << jj);
            }
        }
        s_sup[(i << 5) + w] = m;
        if (m) s_rowany[i] = 1;   // benign race, write of 1 only
    }
    __syncthreads();

    // -------- Phase 7: sequential greedy scan (one warp, skip-list) --------
    if (tid < 32) {
        unsigned int remv = 0;   // lane holds removed-mask word `lane`
        for (int w = 0; w < 32; w++) {
            unsigned int rm = __shfl_sync(FULL, remv, w);
            unsigned int vw = s_validw[w];
            unsigned int kw = 0;
            unsigned int cand = vw & ~rm;
            while (cand) {
                int bit = __ffs(cand) - 1;
                kw |= (1u << bit);
                int i = (w << 5) + bit;
                if (s_rowany[i]) {
                    remv |= s_sup[(i << 5) + lane];
                    rm = __shfl_sync(FULL, remv, w);
                    cand = vw & ~rm & (0xFFFFFFFEu << bit);
                } else {
                    cand &= ~(1u << bit);
                }
            }
            if (lane == 0) s_keepw[w] = kw;
        }
    }
    __syncthreads();

    // -------- Phase 8: write outputs --------
    const bool write_keep = (out_size >= BB * KC * 6);
    for (int t = tid; t < KC; t += NT) {
        bool kept = (s_keepw[t >> 5] >> (t & 31)) & 1u;
        float kf = kept ? 1.0f : 0.0f;
        float sc = __uint_as_float((unsigned int)(s_keys[t] >> 32));
        size_t base = ((size_t)b * KC + t) * 5;
        out[base + 0] = __fmul_rn(s_x1[t], kf);
        out[base + 1] = __fmul_rn(s_y1[t], kf);
        out[base + 2] = __fmul_rn(s_x2[t], kf);
        out[base + 3] = __fmul_rn(s_y2[t], kf);
        out[base + 4] = __fmul_rn(sc, kf);
        if (write_keep)
            out[(size_t)BB * KC * 5 + (size_t)b * KC + t] = kf;
    }
}

extern "C" void kernel_launch(void* const* d_in, const int* in_sizes, int n_in,
                              void* d_out, int out_size)
{
    (void)in_sizes; (void)n_in;
    cudaFuncSetAttribute(facedet_kernel,
                         cudaFuncAttributeMaxDynamicSharedMemorySize, SM_TOTAL);
    facedet_kernel<<<BB, NT, SM_TOTAL>>>(
        (const float*)d_in[0],   // locs  [B, NP, 4]
        (const float*)d_in[1],   // confs [B, NP, 2]
        (const float*)d_in[2],   // priors [NP, 4]
        (float*)d_out, out_size);
}

// round 3
// speedup vs baseline: 6.3786x; 1.3049x over previous
#include <cuda_runtime.h>
#include <cstdint>

// Problem constants
#define NP 21504   // priors per image
#define HALF 10752 // NP/2
#define KC 1024    // top-k
#define BB 64      // batch
#define NT 512     // threads per block
#define WORDS 32   // KC/32 mask words
#define CCAP 2048  // candidate buffer (>= KC + ties)

// ---------------- global scratch (device globals: no allocs) ----------------
__device__ float              g_scores[BB * NP];            // 5.5 MB
__device__ unsigned int       g_hist2[BB * 2 * 256];        // per-slice top-byte hist
__device__ unsigned long long g_keys[BB * KC];              // sorted top-K keys
__device__ float              g_bx1[BB * KC];
__device__ float              g_by1[BB * KC];
__device__ float              g_bx2[BB * KC];
__device__ float              g_by2[BB * KC];
__device__ float              g_bar[BB * KC];
__device__ unsigned int       g_sup[BB * WORDS * KC];       // w-major per image, 8 MB
__device__ unsigned int       g_rowany2[BB * 2 * 32];       // per-slice rowany bitmask
__device__ unsigned int       g_validw[BB * 32];

// ======================= K1: softmax + top-byte histogram ====================
__global__ __launch_bounds__(NT, 1)
void k1_score(const float* __restrict__ confs)
{
    __shared__ unsigned int s_hist[256];
    const int b    = blockIdx.y;
    const int half = blockIdx.x;
    const int tid  = threadIdx.x;
    const int lane = tid & 31;
    const unsigned FULL = 0xffffffffu;

    for (int i = tid; i < 256; i += NT) s_hist[i] = 0;
    __syncthreads();

    const float* conf = confs + (size_t)b * NP * 2;
    const int n0 = half * HALF;
    for (int n = n0 + tid; n < n0 + HALF; n += NT) {
        float2 c = __ldg((const float2*)(conf + 2 * n));
        float m  = fmaxf(c.x, c.y);
        float e0 = expf(__fsub_rn(c.x, m));
        float e1 = expf(__fsub_rn(c.y, m));
        float s  = __fdiv_rn(e1, __fadd_rn(e0, e1));
        g_scores[(size_t)b * NP + n] = s;
        unsigned int digit = __float_as_uint(s) >> 24;
        unsigned int mmask = __match_any_sync(FULL, digit);
        if (lane == (__ffs(mmask) - 1))
            atomicAdd(&s_hist[digit], __popc(mmask));
    }
    __syncthreads();
    if (tid < 256) g_hist2[((b * 2 + half) << 8) + tid] = s_hist[tid];
}

// ======================= K2: radix select + sort + decode ====================
#define K2_SCORES 0        // 86016
#define K2_KEYS   86016    // 16384 (u64[2048])
#define K2_HIST   102400   // 1024
#define K2_SCAN   103424   // 1024
#define K2_MISC   104448
#define K2_TOTAL  104512

__global__ __launch_bounds__(NT, 1)
void k2_select(const float* __restrict__ locs,
               const float* __restrict__ priors)
{
    extern __shared__ unsigned char sm[];
    float*              s_scores = (float*)(sm + K2_SCORES);
    unsigned long long* s_keys   = (unsigned long long*)(sm + K2_KEYS);
    unsigned int*       s_hist   = (unsigned int*)(sm + K2_HIST);
    unsigned int*       s_scan   = (unsigned int*)(sm + K2_SCAN);
    int*                s_misc   = (int*)(sm + K2_MISC);

    const int b    = blockIdx.x;
    const int tid  = threadIdx.x;
    const int lane = tid & 31;
    const unsigned FULL = 0xffffffffu;

    // stage scores into SMEM (float4)
    {
        const float4* gs = (const float4*)(g_scores + (size_t)b * NP);
        float4* ss = (float4*)s_scores;
        for (int i = tid; i < NP / 4; i += NT) ss[i] = gs[i];
    }
    // pass 1 from precomputed histograms
    if (tid < 256)
        s_scan[tid] = g_hist2[((b * 2) << 8) + tid] +
                      g_hist2[((b * 2 + 1) << 8) + tid];
    __syncthreads();
    for (int off = 1; off < 256; off <<= 1) {
        unsigned int v = 0;
        if (tid < 256) {
            v = s_scan[tid];
            if (tid + off < 256) v += s_scan[tid + off];
        }
        __syncthreads();
        if (tid < 256) s_scan[tid] = v;
        __syncthreads();
    }
    if (tid < 256) {
        unsigned int sb  = s_scan[tid];
        unsigned int sb1 = (tid < 255) ? s_scan[tid + 1] : 0u;
        if (sb >= (unsigned int)KC && sb1 < (unsigned int)KC) {
            s_misc[1] = tid;
            s_misc[2] = (int)sb1;
        }
    }
    __syncthreads();
    if (tid == 0) {
        s_misc[4] = (int)((unsigned int)s_misc[1] << 24);
        s_misc[3] = KC - s_misc[2];
    }
    __syncthreads();

    // passes 2..4 on SMEM scores
    #pragma unroll
    for (int shift = 16; shift >= 0; shift -= 8) {
        const unsigned int pref = (unsigned int)s_misc[4];
        const int rem = s_misc[3];
        for (int i = tid; i < 256; i += NT) s_hist[i] = 0;
        __syncthreads();
        for (int n = tid; n < NP; n += NT) {
            unsigned int sb = __float_as_uint(s_scores[n]);
            bool valid = ((sb >> (shift + 8)) == (pref >> (shift + 8)));
            unsigned int digit = (sb >> shift) & 255u;
            unsigned int mkey  = valid ? digit : 0xFFFFFFFFu;
            unsigned int mmask = __match_any_sync(FULL, mkey);
            if (valid && lane == (__ffs(mmask) - 1))
                atomicAdd(&s_hist[digit], __popc(mmask));
        }
        __syncthreads();
        if (tid < 256) s_scan[tid] = s_hist[tid];
        __syncthreads();
        for (int off = 1; off < 256; off <<= 1) {
            unsigned int v = 0;
            if (tid < 256) {
                v = s_scan[tid];
                if (tid + off < 256) v += s_scan[tid + off];
            }
            __syncthreads();
            if (tid < 256) s_scan[tid] = v;
            __syncthreads();
        }
        if (tid < 256) {
            unsigned int sb  = s_scan[tid];
            unsigned int sb1 = (tid < 255) ? s_scan[tid + 1] : 0u;
            if (sb >= (unsigned int)rem && sb1 < (unsigned int)rem) {
                s_misc[1] = tid;
                s_misc[2] = (int)sb1;
            }
        }
        __syncthreads();
        if (tid == 0) {
            s_misc[4] = (int)((unsigned int)s_misc[4] |
                              ((unsigned int)s_misc[1] << shift));
            s_misc[3] = s_misc[3] - s_misc[2];
        }
        __syncthreads();
    }
    const unsigned int Ts = (unsigned int)s_misc[4];
    if (tid == 0) s_misc[0] = 0;
    for (int i = tid; i < CCAP; i += NT) s_keys[i] = 0ULL;
    __syncthreads();

    // collect keys with score >= Ts (warp-aggregated)
    for (int n = tid; n < NP; n += NT) {
        unsigned int sb = __float_as_uint(s_scores[n]);
        bool c = (sb >= Ts);
        unsigned int bal = __ballot_sync(FULL, c);
        if (bal) {
            int leader = __ffs(bal) - 1;
            int base = 0;
            if (lane == leader) base = atomicAdd(&s_misc[0], __popc(bal));
            base = __shfl_sync(FULL, base, leader);
            if (c) {
                int p = base + __popc(bal & ((1u << lane) - 1u));
                if (p < CCAP)
                    s_keys[p] = ((unsigned long long)sb << 32) |
                                (unsigned int)(~n);
            }
        }
    }
    __syncthreads();

    // bitonic sort CCAP keys descending
    for (int k = 2; k <= CCAP; k <<= 1) {
        for (int j = k >> 1; j > 0; j >>= 1) {
            for (int i = tid; i < CCAP; i += NT) {
                int ixj = i ^ j;
                if (ixj > i) {
                    unsigned long long a = s_keys[i];
                    unsigned long long c = s_keys[ixj];
                    bool desc = ((i & k) == 0);
                    if (desc ? (a < c) : (a > c)) {
                        s_keys[i] = c; s_keys[ixj] = a;
                    }
                }
            }
            __syncthreads();
        }
    }

    // decode boxes (match XLA: no FMA contraction) + write scratch
    const float* loc = locs + (size_t)b * NP * 4;
    for (int t = tid; t < KC; t += NT) {
        unsigned long long key = s_keys[t];
        int idx = (int)(~(unsigned int)key);
        float4 l = __ldg((const float4*)(loc + 4 * (size_t)idx));
        float4 p = __ldg((const float4*)(priors + 4 * (size_t)idx));
        float cx = __fadd_rn(p.x, __fmul_rn(__fmul_rn(l.x, 0.1f), p.z));
        float cy = __fadd_rn(p.y, __fmul_rn(__fmul_rn(l.y, 0.1f), p.w));
        float w  = __fmul_rn(p.z, expf(__fmul_rn(l.z, 0.2f)));
        float h  = __fmul_rn(p.w, expf(__fmul_rn(l.w, 0.2f)));
        float x1 = __fsub_rn(cx, __fdiv_rn(w, 2.0f));
        float y1 = __fsub_rn(cy, __fdiv_rn(h, 2.0f));
        float x2 = __fadd_rn(x1, w);
        float y2 = __fadd_rn(y1, h);
        size_t o = (size_t)b * KC + t;
        g_bx1[o] = x1; g_by1[o] = y1; g_bx2[o] = x2; g_by2[o] = y2;
        float aw = fmaxf(__fsub_rn(x2, x1), 0.0f);
        float ah = fmaxf(__fsub_rn(y2, y1), 0.0f);
        g_bar[o] = __fmul_rn(aw, ah);
        g_keys[o] = key;
        float sc = __uint_as_float((unsigned int)(key >> 32));
        unsigned int bal = __ballot_sync(FULL, sc > 0.5f);
        if (lane == 0) g_validw[b * 32 + (t >> 5)] = bal;
    }
}

// ======================= K3: suppression bitmatrix ===========================
__global__ __launch_bounds__(NT, 1)
void k3_supmat()
{
    __shared__ float s_x1[KC], s_y1[KC], s_x2[KC], s_y2[KC], s_area[KC];
    __shared__ unsigned char s_rowflag[KC];

    const int b    = blockIdx.y;
    const int half = blockIdx.x;
    const int tid  = threadIdx.x;
    const int lane = tid & 31;

    for (int t = tid; t < KC; t += NT) {
        size_t o = (size_t)b * KC + t;
        s_x1[t] = g_bx1[o]; s_y1[t] = g_by1[o];
        s_x2[t] = g_bx2[o]; s_y2[t] = g_by2[o];
        s_area[t] = g_bar[o];
        s_rowflag[t] = 0;
    }
    __syncthreads();

    unsigned int* supb = g_sup + (size_t)b * WORDS * KC;
    for (int t = tid; t < 16 * KC; t += NT) {
        int w  = half * 16 + (t >> 10);  // warp-uniform
        int i  = t & 1023;               // consecutive across lanes
        int j0 = w << 5;
        unsigned int m = 0;
        if (j0 + 31 > i) {
            float xi1 = s_x1[i], yi1 = s_y1[i];
            float xi2 = s_x2[i], yi2 = s_y2[i];
            float ai  = s_area[i];
            #pragma unroll 4
            for (int jj = 0; jj < 32; jj++) {
                int j = j0 + jj;         // warp-uniform -> broadcast LDS
                if (j <= i) continue;
                float lx = fmaxf(xi1, s_x1[j]);
                float ly = fmaxf(yi1, s_y1[j]);
                float rx = fminf(xi2, s_x2[j]);
                float ry = fminf(yi2, s_y2[j]);
                float ww = fmaxf(__fsub_rn(rx, lx), 0.0f);
                float hh = fmaxf(__fsub_rn(ry, ly), 0.0f);
                float inter = __fmul_rn(ww, hh);
                float um = __fsub_rn(__fadd_rn(ai, s_area[j]), inter);
                float t4 = __fmul_rn(0.4f, um);
                bool hi = inter > __fmul_rn(t4, 1.00002f);
                bool lo = inter < __fmul_rn(t4, 0.99998f);
                bool sup = hi;
                if (!hi && !lo)  // rare: rounding band -> exact
                    sup = (__fdiv_rn(inter, fmaxf(um, 1e-9f)) > 0.4f);
                if (sup) m |= (1u << jj);
            }
        }
        supb[(w << 10) + i] = m;         // w-major: coalesced across lanes
        if (m) s_rowflag[i] = 1;         // benign race (writes of 1)
    }
    __syncthreads();
    for (int r = tid; r < KC; r += NT) {
        unsigned int bal = __ballot_sync(0xffffffffu, s_rowflag[r] != 0);
        if (lane == 0) g_rowany2[((b * 2 + half) << 5) + (r >> 5)] = bal;
    }
}

// ======================= K4: greedy scan + outputs ===========================
#define PAD 33
#define K4_SUP    0                     // 1024*33*4 = 135168
#define K4_BX1    135168
#define K4_BY1    139264
#define K4_BX2    143360
#define K4_BY2    147456
#define K4_ROWANY 151552                // u32[32]
#define K4_VALW   151680                // u32[32]
#define K4_KEEPW  151808                // u32[32]
#define K4_TOTAL  151936

__global__ __launch_bounds__(NT, 1)
void k4_scan(float* __restrict__ out, int out_size)
{
    extern __shared__ unsigned char sm[];
    unsigned int* s_sup    = (unsigned int*)(sm + K4_SUP);
    float*        s_x1     = (float*)(sm + K4_BX1);
    float*        s_y1     = (float*)(sm + K4_BY1);
    float*        s_x2     = (float*)(sm + K4_BX2);
    float*        s_y2     = (float*)(sm + K4_BY2);
    unsigned int* s_rowany = (unsigned int*)(sm + K4_ROWANY);
    unsigned int* s_validw = (unsigned int*)(sm + K4_VALW);
    unsigned int* s_keepw  = (unsigned int*)(sm + K4_KEEPW);

    const int b    = blockIdx.x;
    const int tid  = threadIdx.x;
    const int lane = tid & 31;
    const unsigned FULL = 0xffffffffu;

    // stage sup matrix (global w-major -> SMEM row-major, pad 33 kills conflicts)
    const unsigned int* supb = g_sup + (size_t)b * WORDS * KC;
    for (int t = tid; t < WORDS * KC; t += NT) {
        int w = t >> 10;
        int i = t & 1023;
        s_sup[i * PAD + w] = supb[t];
    }
    for (int t = tid; t < KC; t += NT) {
        size_t o = (size_t)b * KC + t;
        s_x1[t] = g_bx1[o]; s_y1[t] = g_by1[o];
        s_x2[t] = g_bx2[o]; s_y2[t] = g_by2[o];
    }
    if (tid < 32) {
        s_rowany[tid] = g_rowany2[((b * 2) << 5) + tid] |
                        g_rowany2[((b * 2 + 1) << 5) + tid];
        s_validw[tid] = g_validw[b * 32 + tid];
    }
    __syncthreads();

    // sequential greedy scan (one warp, skip-list)
    if (tid < 32) {
        unsigned int remv = 0;
        for (int w = 0; w < 32; w++) {
            unsigned int rm = __shfl_sync(FULL, remv, w);
            unsigned int vw = s_validw[w];
            unsigned int ra = s_rowany[w];
            unsigned int kw = 0;
            unsigned int cand = vw & ~rm;
            while (cand) {
                int bit = __ffs(cand) - 1;
                kw |= (1u << bit);
                if ((ra >> bit) & 1u) {
                    int i = (w << 5) + bit;
                    remv |= s_sup[i * PAD + lane];
                    rm = __shfl_sync(FULL, remv, w);
                    cand = vw & ~rm & (0xFFFFFFFEu << bit);
                } else {
                    cand &= ~(1u << bit);
                }
            }
            if (lane == 0) s_keepw[w] = kw;
        }
    }
    __syncthreads();

    // write outputs: dets [B,KC,5], keep [B,KC]
    const bool write_keep = (out_size >= BB * KC * 6);
    for (int t = tid; t < KC; t += NT) {
        bool kept = (s_keepw[t >> 5] >> (t & 31)) & 1u;
        float kf = kept ? 1.0f : 0.0f;
        float sc = __uint_as_float(
            (unsigned int)(g_keys[(size_t)b * KC + t] >> 32));
        size_t base = ((size_t)b * KC + t) * 5;
        out[base + 0] = __fmul_rn(s_x1[t], kf);
        out[base + 1] = __fmul_rn(s_y1[t], kf);
        out[base + 2] = __fmul_rn(s_x2[t], kf);
        out[base + 3] = __fmul_rn(s_y2[t], kf);
        out[base + 4] = __fmul_rn(sc, kf);
        if (write_keep)
            out[(size_t)BB * KC * 5 + (size_t)b * KC + t] = kf;
    }
}

// ======================= launch ==============================================
extern "C" void kernel_launch(void* const* d_in, const int* in_sizes, int n_in,
                              void* d_out, int out_size)
{
    (void)in_sizes; (void)n_in;
    static bool attr_done = false;
    if (!attr_done) {
        cudaFuncSetAttribute(k2_select,
            cudaFuncAttributeMaxDynamicSharedMemorySize, K2_TOTAL);
        cudaFuncSetAttribute(k4_scan,
            cudaFuncAttributeMaxDynamicSharedMemorySize, K4_TOTAL);
        attr_done = true;
    }
    const float* locs   = (const float*)d_in[0];
    const float* confs  = (const float*)d_in[1];
    const float* priors = (const float*)d_in[2];
    float* out = (float*)d_out;

    k1_score<<<dim3(2, BB), NT>>>(confs);
    k2_select<<<BB, NT, K2_TOTAL>>>(locs, priors);
    k3_supmat<<<dim3(2, BB), NT>>>();
    k4_scan<<<BB, NT, K4_TOTAL>>>(out, out_size);
}

// round 4
// speedup vs baseline: 6.5274x; 1.0233x over previous
#include <cuda_runtime.h>
#include <cstdint>

// Problem constants
#define NP 21504   // priors per image
#define KC 1024    // top-k
#define BB 64      // batch
#define NT 512     // threads per block
#define WORDS 32   // KC/32 mask words
#define CCAP 2048  // candidate buffer (>= KC + ties)
#define PAD 33

// ---------------- global scratch (device globals: no allocs) ----------------
__device__ unsigned long long g_keys[BB * KC];   // sorted top-K keys
__device__ float              g_bx1[BB * KC];
__device__ float              g_by1[BB * KC];
__device__ float              g_bx2[BB * KC];
__device__ float              g_by2[BB * KC];
__device__ float              g_bar[BB * KC];

// ===================== kA: softmax + select + sort + decode ==================
// SMEM layout (bytes)
#define KA_SCORES 0        // 86016: float[NP]
#define KA_KEYS   86016    // 16384: u64[2048]
#define KA_HIST   102400   // 1024
#define KA_SCAN   103424   // 1024
#define KA_MISC   104448   // 32: ints
#define KA_WSUM   104480   // 32: u32[8]
#define KA_TOTAL  104512

__global__ __launch_bounds__(NT, 1)
void kA_select(const float* __restrict__ locs,
               const float* __restrict__ confs,
               const float* __restrict__ priors)
{
    extern __shared__ unsigned char sm[];
    float*              s_scores = (float*)(sm + KA_SCORES);
    unsigned long long* s_keys   = (unsigned long long*)(sm + KA_KEYS);
    unsigned int*       s_hist   = (unsigned int*)(sm + KA_HIST);
    unsigned int*       s_scan   = (unsigned int*)(sm + KA_SCAN);
    int*                s_misc   = (int*)(sm + KA_MISC);
    unsigned int*       s_wsum   = (unsigned int*)(sm + KA_WSUM);

    const int b    = blockIdx.x;
    const int tid  = threadIdx.x;
    const int lane = tid & 31;
    const int wid  = tid >> 5;
    const unsigned FULL = 0xffffffffu;

    // ---- Phase 1: softmax (exact XLA sequence) + pass-1 histogram ----
    for (int i = tid; i < 256; i += NT) s_hist[i] = 0;
    __syncthreads();
    const float* conf = confs + (size_t)b * NP * 2;
    for (int n = tid; n < NP; n += NT) {
        float2 c = __ldg((const float2*)(conf + 2 * n));
        float m  = fmaxf(c.x, c.y);
        float e0 = expf(__fsub_rn(c.x, m));
        float e1 = expf(__fsub_rn(c.y, m));
        float s  = __fdiv_rn(e1, __fadd_rn(e0, e1));
        s_scores[n] = s;
        unsigned int digit = __float_as_uint(s) >> 24;
        unsigned int mmask = __match_any_sync(FULL, digit);
        if (lane == (__ffs(mmask) - 1))
            atomicAdd(&s_hist[digit], __popc(mmask));
    }
    if (tid == 0) { s_misc[3] = KC; s_misc[4] = 0; }  // rem, prefix
    __syncthreads();

    // ---- Phase 2: 4 radix passes (pass 1 hist already built) ----
    #pragma unroll
    for (int shift = 24; shift >= 0; shift -= 8) {
        const unsigned int pref = (unsigned int)s_misc[4];
        const int rem = s_misc[3];
        if (shift != 24) {
            for (int i = tid; i < 256; i += NT) s_hist[i] = 0;
            __syncthreads();
            for (int n = tid; n < NP; n += NT) {
                unsigned int sb = __float_as_uint(s_scores[n]);
                bool valid = ((sb >> (shift + 8)) == (pref >> (shift + 8)));
                unsigned int digit = (sb >> shift) & 255u;
                unsigned int mkey  = valid ? digit : 0xFFFFFFFFu;
                unsigned int mmask = __match_any_sync(FULL, mkey);
                if (valid && lane == (__ffs(mmask) - 1))
                    atomicAdd(&s_hist[digit], __popc(mmask));
            }
            __syncthreads();
        }
        // suffix sums over 256 bins: warp shfl + cross-warp
        unsigned int v = 0;
        if (tid < 256) {
            v = s_hist[tid];
            #pragma unroll
            for (int off = 1; off < 32; off <<= 1) {
                unsigned int u = __shfl_down_sync(FULL, v, off);
                if (lane + off < 32) v += u;
            }
            if (lane == 0) s_wsum[wid] = v;   // warp total
        }
        __syncthreads();
        if (tid < 256) {
            unsigned int add = 0;
            for (int w2 = wid + 1; w2 < 8; w2++) add += s_wsum[w2];
            s_scan[tid] = v + add;
        }
        __syncthreads();
        if (tid < 256) {
            unsigned int sb  = s_scan[tid];
            unsigned int sb1 = (tid < 255) ? s_scan[tid + 1] : 0u;
            if (sb >= (unsigned int)rem && sb1 < (unsigned int)rem) {
                s_misc[1] = tid;
                s_misc[2] = (int)sb1;
            }
        }
        __syncthreads();
        if (tid == 0) {
            s_misc[4] = (int)((unsigned int)s_misc[4] |
                              ((unsigned int)s_misc[1] << shift));
            s_misc[3] = s_misc[3] - s_misc[2];
        }
        __syncthreads();
    }
    const unsigned int Ts = (unsigned int)s_misc[4];
    if (tid == 0) s_misc[0] = 0;
    for (int i = tid; i < CCAP; i += NT) s_keys[i] = 0ULL;
    __syncthreads();

    // ---- Phase 3: collect keys with score >= Ts (warp-aggregated) ----
    for (int n = tid; n < NP; n += NT) {
        unsigned int sb = __float_as_uint(s_scores[n]);
        bool c = (sb >= Ts);
        unsigned int bal = __ballot_sync(FULL, c);
        if (bal) {
            int leader = __ffs(bal) - 1;
            int base = 0;
            if (lane == leader) base = atomicAdd(&s_misc[0], __popc(bal));
            base = __shfl_sync(FULL, base, leader);
            if (c) {
                int p = base + __popc(bal & ((1u << lane) - 1u));
                if (p < CCAP)
                    s_keys[p] = ((unsigned long long)sb << 32) |
                                (unsigned int)(~n);
            }
        }
    }
    __syncthreads();

    // ---- Phase 4: bitonic sort CCAP keys descending ----
    for (int k = 2; k <= CCAP; k <<= 1) {
        for (int j = k >> 1; j > 0; j >>= 1) {
            for (int i = tid; i < CCAP; i += NT) {
                int ixj = i ^ j;
                if (ixj > i) {
                    unsigned long long a = s_keys[i];
                    unsigned long long c = s_keys[ixj];
                    bool desc = ((i & k) == 0);
                    if (desc ? (a < c) : (a > c)) {
                        s_keys[i] = c; s_keys[ixj] = a;
                    }
                }
            }
            __syncthreads();
        }
    }

    // ---- Phase 5: decode boxes (no FMA contraction) + write scratch ----
    const float* loc = locs + (size_t)b * NP * 4;
    for (int t = tid; t < KC; t += NT) {
        unsigned long long key = s_keys[t];
        int idx = (int)(~(unsigned int)key);
        float4 l = __ldg((const float4*)(loc + 4 * (size_t)idx));
        float4 p = __ldg((const float4*)(priors + 4 * (size_t)idx));
        float cx = __fadd_rn(p.x, __fmul_rn(__fmul_rn(l.x, 0.1f), p.z));
        float cy = __fadd_rn(p.y, __fmul_rn(__fmul_rn(l.y, 0.1f), p.w));
        float w  = __fmul_rn(p.z, expf(__fmul_rn(l.z, 0.2f)));
        float h  = __fmul_rn(p.w, expf(__fmul_rn(l.w, 0.2f)));
        float x1 = __fsub_rn(cx, __fdiv_rn(w, 2.0f));
        float y1 = __fsub_rn(cy, __fdiv_rn(h, 2.0f));
        float x2 = __fadd_rn(x1, w);
        float y2 = __fadd_rn(y1, h);
        size_t o = (size_t)b * KC + t;
        g_bx1[o] = x1; g_by1[o] = y1; g_bx2[o] = x2; g_by2[o] = y2;
        float aw = fmaxf(__fsub_rn(x2, x1), 0.0f);
        float ah = fmaxf(__fsub_rn(y2, y1), 0.0f);
        g_bar[o] = __fmul_rn(aw, ah);
        g_keys[o] = key;
    }
}

// ===================== kB: suppression matrix + scan + output ===============
#define KB_SUP    0                       // 1024*33*4 = 135168
#define KB_X1     135168                  // 4096 each
#define KB_Y1     139264
#define KB_X2     143360
#define KB_Y2     147456
#define KB_AREA   151552
#define KB_SC     155648
#define KB_ROWF   159744                  // 1024 bytes row flags
#define KB_RAW    160768                  // u32[32] rowany bitmask
#define KB_VALW   160896                  // u32[32]
#define KB_KEEPW  161024                  // u32[32]
#define KB_TOTAL  161152

__global__ __launch_bounds__(NT, 1)
void kB_nms(float* __restrict__ out, int out_size)
{
    extern __shared__ unsigned char sm[];
    unsigned int*  s_sup   = (unsigned int*)(sm + KB_SUP);
    float*         s_x1    = (float*)(sm + KB_X1);
    float*         s_y1    = (float*)(sm + KB_Y1);
    float*         s_x2    = (float*)(sm + KB_X2);
    float*         s_y2    = (float*)(sm + KB_Y2);
    float*         s_area  = (float*)(sm + KB_AREA);
    float*         s_sc    = (float*)(sm + KB_SC);
    unsigned char* s_rowf  = (unsigned char*)(sm + KB_ROWF);
    unsigned int*  s_raw   = (unsigned int*)(sm + KB_RAW);
    unsigned int*  s_validw= (unsigned int*)(sm + KB_VALW);
    unsigned int*  s_keepw = (unsigned int*)(sm + KB_KEEPW);

    const int b    = blockIdx.x;
    const int tid  = threadIdx.x;
    const int lane = tid & 31;
    const unsigned FULL = 0xffffffffu;

    // ---- stage boxes/scores ----
    for (int t = tid; t < KC; t += NT) {
        size_t o = (size_t)b * KC + t;
        s_x1[t] = g_bx1[o]; s_y1[t] = g_by1[o];
        s_x2[t] = g_bx2[o]; s_y2[t] = g_by2[o];
        s_area[t] = g_bar[o];
        float sc = __uint_as_float((unsigned int)(g_keys[o] >> 32));
        s_sc[t] = sc;
        s_rowf[t] = 0;
        unsigned int bal = __ballot_sync(FULL, sc > 0.5f);
        if (lane == 0) s_validw[t >> 5] = bal;
    }
    __syncthreads();

    // ---- suppression bitmatrix into padded SMEM (lanes = rows) ----
    for (int t = tid; t < WORDS * KC; t += NT) {
        int w  = t >> 10;        // warp-uniform word
        int i  = t & 1023;       // consecutive across lanes
        int j0 = w << 5;
        unsigned int m = 0;
        if (j0 + 31 > i) {
            float xi1 = s_x1[i], yi1 = s_y1[i];
            float xi2 = s_x2[i], yi2 = s_y2[i];
            float ai  = s_area[i];
            #pragma unroll 4
            for (int jj = 0; jj < 32; jj++) {
                int j = j0 + jj;     // warp-uniform -> broadcast LDS
                if (j <= i) continue;
                float lx = fmaxf(xi1, s_x1[j]);
                float ly = fmaxf(yi1, s_y1[j]);
                float rx = fminf(xi2, s_x2[j]);
                float ry = fminf(yi2, s_y2[j]);
                float ww = fmaxf(__fsub_rn(rx, lx), 0.0f);
                float hh = fmaxf(__fsub_rn(ry, ly), 0.0f);
                float inter = __fmul_rn(ww, hh);
                float um = __fsub_rn(__fadd_rn(ai, s_area[j]), inter);
                float t4 = __fmul_rn(0.4f, um);
                bool hi = inter > __fmul_rn(t4, 1.00002f);
                bool lo = inter < __fmul_rn(t4, 0.99998f);
                bool sup = hi;
                if (!hi && !lo)  // rare rounding band -> exact
                    sup = (__fdiv_rn(inter, fmaxf(um, 1e-9f)) > 0.4f);
                if (sup) m |= (1u << jj);
            }
        }
        s_sup[i * PAD + w] = m;   // bank (i+w)&31: conflict-free
        if (m) s_rowf[i] = 1;     // benign race (writes of 1)
    }
    __syncthreads();
    for (int r = tid; r < KC; r += NT) {
        unsigned int bal = __ballot_sync(FULL, s_rowf[r] != 0);
        if (lane == 0) s_raw[r >> 5] = bal;
    }
    __syncthreads();

    // ---- greedy scan: one warp, suppressors-only loop, no shfl in chain ----
    if (tid < 32) {
        unsigned int remv = 0;   // lane holds removed-mask word `lane`
        for (int w = 0; w < 32; w++) {
            unsigned int rm = __shfl_sync(FULL, remv, w);  // once per word
            unsigned int vw = s_validw[w];
            unsigned int ra = s_raw[w];
            unsigned int kw = 0;
            unsigned int pending = vw & ra;    // suppressor candidates
            unsigned int scand;
            while ((scand = pending & ~rm) != 0) {
                int bit = __ffs(scand) - 1;
                pending &= ~(1u << bit);
                kw |= (1u << bit);             // kept suppressor
                int i = (w << 5) + bit;
                unsigned int rowl = s_sup[i * PAD + lane]; // per-lane word
                unsigned int roww = s_sup[i * PAD + w];    // broadcast
                remv |= rowl;
                rm   |= roww;                  // local update, no shfl
            }
            kw |= vw & ~ra & ~rm;  // non-suppressors kept iff never removed
            if (lane == 0) s_keepw[w] = kw;
        }
    }
    __syncthreads();

    // ---- outputs: dets [B,KC,5], keep [B,KC] ----
    const bool write_keep = (out_size >= BB * KC * 6);
    for (int t = tid; t < KC; t += NT) {
        bool kept = (s_keepw[t >> 5] >> (t & 31)) & 1u;
        float kf = kept ? 1.0f : 0.0f;
        size_t base = ((size_t)b * KC + t) * 5;
        out[base + 0] = __fmul_rn(s_x1[t], kf);
        out[base + 1] = __fmul_rn(s_y1[t], kf);
        out[base + 2] = __fmul_rn(s_x2[t], kf);
        out[base + 3] = __fmul_rn(s_y2[t], kf);
        out[base + 4] = __fmul_rn(s_sc[t], kf);
        if (write_keep)
            out[(size_t)BB * KC * 5 + (size_t)b * KC + t] = kf;
    }
}

// ======================= launch ==============================================
extern "C" void kernel_launch(void* const* d_in, const int* in_sizes, int n_in,
                              void* d_out, int out_size)
{
    (void)in_sizes; (void)n_in;
    cudaFuncSetAttribute(kA_select,
        cudaFuncAttributeMaxDynamicSharedMemorySize, KA_TOTAL);
    cudaFuncSetAttribute(kB_nms,
        cudaFuncAttributeMaxDynamicSharedMemorySize, KB_TOTAL);
    const float* locs   = (const float*)d_in[0];
    const float* confs  = (const float*)d_in[1];
    const float* priors = (const float*)d_in[2];
    float* out = (float*)d_out;

    kA_select<<<BB, NT, KA_TOTAL>>>(locs, confs, priors);
    kB_nms<<<BB, NT, KB_TOTAL>>>(out, out_size);
}

// round 5
// speedup vs baseline: 9.2246x; 1.4132x over previous
#include <cuda_runtime.h>
#include <cstdint>

// Problem constants
#define NP 21504   // priors per image
#define KC 1024    // top-k
#define BB 64      // batch
#define NT 512     // threads per block
#define WORDS 32   // KC/32 mask words
#define CCAP 2048  // candidate buffer (>= KC + ties)
#define PAD 33
#define SLICES 4   // supmat blocks per image
#define WPS 8      // words per slice (WORDS/SLICES)

// ---------------- global scratch (device globals: no allocs) ----------------
__device__ unsigned long long g_keys[BB * KC];
__device__ float              g_bx1[BB * KC];
__device__ float              g_by1[BB * KC];
__device__ float              g_bx2[BB * KC];
__device__ float              g_by2[BB * KC];
__device__ float              g_bar[BB * KC];
__device__ unsigned int       g_sup[BB * WORDS * KC];       // w-major per image
__device__ unsigned int       g_rowany[BB * SLICES * 32];   // per-slice bitmask

// ===================== kA: softmax + select + sort + decode ==================
#define KA_SCORES 0        // 86016: float[NP]
#define KA_KEYS   86016    // 16384: u64[2048]
#define KA_HIST   102400   // 1024
#define KA_SCAN   103424   // 1024
#define KA_MISC   104448   // 32
#define KA_WSUM   104480   // 32
#define KA_TOTAL  104512

__global__ __launch_bounds__(NT, 1)
void kA_select(const float* __restrict__ locs,
               const float* __restrict__ confs,
               const float* __restrict__ priors)
{
    extern __shared__ unsigned char sm[];
    float*              s_scores = (float*)(sm + KA_SCORES);
    unsigned long long* s_keys   = (unsigned long long*)(sm + KA_KEYS);
    unsigned int*       s_hist   = (unsigned int*)(sm + KA_HIST);
    unsigned int*       s_scan   = (unsigned int*)(sm + KA_SCAN);
    int*                s_misc   = (int*)(sm + KA_MISC);
    unsigned int*       s_wsum   = (unsigned int*)(sm + KA_WSUM);

    const int b    = blockIdx.x;
    const int tid  = threadIdx.x;
    const int lane = tid & 31;
    const int wid  = tid >> 5;
    const unsigned FULL = 0xffffffffu;

    // ---- Phase 1: softmax (exact XLA sequence) + pass-1 histogram ----
    for (int i = tid; i < 256; i += NT) s_hist[i] = 0;
    __syncthreads();
    const float* conf = confs + (size_t)b * NP * 2;
    for (int n = tid; n < NP; n += NT) {
        float2 c = __ldg((const float2*)(conf + 2 * n));
        float m  = fmaxf(c.x, c.y);
        float e0 = expf(__fsub_rn(c.x, m));
        float e1 = expf(__fsub_rn(c.y, m));
        float s  = __fdiv_rn(e1, __fadd_rn(e0, e1));
        s_scores[n] = s;
        unsigned int digit = __float_as_uint(s) >> 24;
        unsigned int mmask = __match_any_sync(FULL, digit);
        if (lane == (__ffs(mmask) - 1))
            atomicAdd(&s_hist[digit], __popc(mmask));
    }
    if (tid == 0) { s_misc[3] = KC; s_misc[4] = 0; }  // rem, prefix
    __syncthreads();

    // ---- Phase 2: 4 radix passes ----
    #pragma unroll
    for (int shift = 24; shift >= 0; shift -= 8) {
        const unsigned int pref = (unsigned int)s_misc[4];
        const int rem = s_misc[3];
        if (shift != 24) {
            for (int i = tid; i < 256; i += NT) s_hist[i] = 0;
            __syncthreads();
            for (int n = tid; n < NP; n += NT) {
                unsigned int sb = __float_as_uint(s_scores[n]);
                bool valid = ((sb >> (shift + 8)) == (pref >> (shift + 8)));
                unsigned int digit = (sb >> shift) & 255u;
                unsigned int mkey  = valid ? digit : 0xFFFFFFFFu;
                unsigned int mmask = __match_any_sync(FULL, mkey);
                if (valid && lane == (__ffs(mmask) - 1))
                    atomicAdd(&s_hist[digit], __popc(mmask));
            }
            __syncthreads();
        }
        // suffix sums over 256 bins: warp shfl + cross-warp
        unsigned int v = 0;
        if (tid < 256) {
            v = s_hist[tid];
            #pragma unroll
            for (int off = 1; off < 32; off <<= 1) {
                unsigned int u = __shfl_down_sync(FULL, v, off);
                if (lane + off < 32) v += u;
            }
            if (lane == 0) s_wsum[wid] = v;
        }
        __syncthreads();
        if (tid < 256) {
            unsigned int add = 0;
            for (int w2 = wid + 1; w2 < 8; w2++) add += s_wsum[w2];
            s_scan[tid] = v + add;
        }
        __syncthreads();
        if (tid < 256) {
            unsigned int sb  = s_scan[tid];
            unsigned int sb1 = (tid < 255) ? s_scan[tid + 1] : 0u;
            if (sb >= (unsigned int)rem && sb1 < (unsigned int)rem) {
                s_misc[1] = tid;
                s_misc[2] = (int)sb1;
            }
        }
        __syncthreads();
        if (tid == 0) {
            s_misc[4] = (int)((unsigned int)s_misc[4] |
                              ((unsigned int)s_misc[1] << shift));
            s_misc[3] = s_misc[3] - s_misc[2];
        }
        __syncthreads();
    }
    const unsigned int Ts = (unsigned int)s_misc[4];
    if (tid == 0) s_misc[0] = 0;
    for (int i = tid; i < CCAP; i += NT) s_keys[i] = 0ULL;
    __syncthreads();

    // ---- Phase 3: collect keys with score >= Ts (warp-aggregated) ----
    for (int n = tid; n < NP; n += NT) {
        unsigned int sb = __float_as_uint(s_scores[n]);
        bool c = (sb >= Ts);
        unsigned int bal = __ballot_sync(FULL, c);
        if (bal) {
            int leader = __ffs(bal) - 1;
            int base = 0;
            if (lane == leader) base = atomicAdd(&s_misc[0], __popc(bal));
            base = __shfl_sync(FULL, base, leader);
            if (c) {
                int p = base + __popc(bal & ((1u << lane) - 1u));
                if (p < CCAP)
                    s_keys[p] = ((unsigned long long)sb << 32) |
                                (unsigned int)(~n);
            }
        }
    }
    __syncthreads();

    // ---- Phase 4: bitonic sort, dynamic size (1024 if no extra ties) ----
    const int SZ = (s_misc[0] <= 1024) ? 1024 : 2048;
    for (int k = 2; k <= SZ; k <<= 1) {
        for (int j = k >> 1; j > 0; j >>= 1) {
            for (int i = tid; i < SZ; i += NT) {
                int ixj = i ^ j;
                if (ixj > i) {
                    unsigned long long a = s_keys[i];
                    unsigned long long c = s_keys[ixj];
                    bool desc = ((i & k) == 0);
                    if (desc ? (a < c) : (a > c)) {
                        s_keys[i] = c; s_keys[ixj] = a;
                    }
                }
            }
            __syncthreads();
        }
    }

    // ---- Phase 5: decode boxes (no FMA contraction) + write scratch ----
    const float* loc = locs + (size_t)b * NP * 4;
    for (int t = tid; t < KC; t += NT) {
        unsigned long long key = s_keys[t];
        int idx = (int)(~(unsigned int)key);
        float4 l = __ldg((const float4*)(loc + 4 * (size_t)idx));
        float4 p = __ldg((const float4*)(priors + 4 * (size_t)idx));
        float cx = __fadd_rn(p.x, __fmul_rn(__fmul_rn(l.x, 0.1f), p.z));
        float cy = __fadd_rn(p.y, __fmul_rn(__fmul_rn(l.y, 0.1f), p.w));
        float w  = __fmul_rn(p.z, expf(__fmul_rn(l.z, 0.2f)));
        float h  = __fmul_rn(p.w, expf(__fmul_rn(l.w, 0.2f)));
        float x1 = __fsub_rn(cx, __fdiv_rn(w, 2.0f));
        float y1 = __fsub_rn(cy, __fdiv_rn(h, 2.0f));
        float x2 = __fadd_rn(x1, w);
        float y2 = __fadd_rn(y1, h);
        size_t o = (size_t)b * KC + t;
        g_bx1[o] = x1; g_by1[o] = y1; g_bx2[o] = x2; g_by2[o] = y2;
        float aw = fmaxf(__fsub_rn(x2, x1), 0.0f);
        float ah = fmaxf(__fsub_rn(y2, y1), 0.0f);
        g_bar[o] = __fmul_rn(aw, ah);
        g_keys[o] = key;
    }
}

// ===================== kS: suppression bitmatrix (4 slices/image) ============
__global__ __launch_bounds__(NT)
void kS_supmat()
{
    __shared__ float s_x1[KC], s_y1[KC], s_x2[KC], s_y2[KC], s_area[KC];
    __shared__ unsigned char s_rowf[KC];

    const int b     = blockIdx.y;
    const int slice = blockIdx.x;
    const int tid   = threadIdx.x;
    const int lane  = tid & 31;

    for (int t = tid; t < KC; t += NT) {
        size_t o = (size_t)b * KC + t;
        s_x1[t] = g_bx1[o]; s_y1[t] = g_by1[o];
        s_x2[t] = g_bx2[o]; s_y2[t] = g_by2[o];
        s_area[t] = g_bar[o];
        s_rowf[t] = 0;
    }
    __syncthreads();

    unsigned int* supb = g_sup + (size_t)b * WORDS * KC;
    for (int t = tid; t < WPS * KC; t += NT) {
        int w  = slice * WPS + (t >> 10);  // warp-uniform
        int i  = t & 1023;                 // consecutive across lanes
        int j0 = w << 5;
        unsigned int m = 0;
        if (j0 + 31 > i) {
            float xi1 = s_x1[i], yi1 = s_y1[i];
            float xi2 = s_x2[i], yi2 = s_y2[i];
            float ai  = s_area[i];
            #pragma unroll 4
            for (int jj = 0; jj < 32; jj++) {
                int j = j0 + jj;           // warp-uniform -> broadcast LDS
                if (j <= i) continue;
                float lx = fmaxf(xi1, s_x1[j]);
                float ly = fmaxf(yi1, s_y1[j]);
                float rx = fminf(xi2, s_x2[j]);
                float ry = fminf(yi2, s_y2[j]);
                float ww = fmaxf(__fsub_rn(rx, lx), 0.0f);
                float hh = fmaxf(__fsub_rn(ry, ly), 0.0f);
                float inter = __fmul_rn(ww, hh);
                float um = __fsub_rn(__fadd_rn(ai, s_area[j]), inter);
                float t4 = __fmul_rn(0.4f, um);
                bool hi = inter > __fmul_rn(t4, 1.00002f);
                bool lo = inter < __fmul_rn(t4, 0.99998f);
                bool sup = hi;
                if (!hi && !lo)  // rare rounding band -> exact
                    sup = (__fdiv_rn(inter, fmaxf(um, 1e-9f)) > 0.4f);
                if (sup) m |= (1u << jj);
            }
        }
        supb[(w << 10) + i] = m;           // coalesced across lanes
        if (m) s_rowf[i] = 1;              // benign race (writes of 1)
    }
    __syncthreads();
    for (int r = tid; r < KC; r += NT) {
        unsigned int bal = __ballot_sync(0xffffffffu, s_rowf[r] != 0);
        if (lane == 0)
            g_rowany[((b * SLICES + slice) << 5) + (r >> 5)] = bal;
    }
}

// ===================== kB: stage + greedy scan + output ======================
#define KB_SUP    0                       // 1024*33*4 = 135168
#define KB_X1     135168
#define KB_Y1     139264
#define KB_X2     143360
#define KB_Y2     147456
#define KB_SC     151552
#define KB_RAW    155648                  // u32[32]
#define KB_VALW   155776                  // u32[32]
#define KB_KEEPW  155904                  // u32[32]
#define KB_TOTAL  156032

__global__ __launch_bounds__(NT, 1)
void kB_scan(float* __restrict__ out, int out_size)
{
    extern __shared__ unsigned char sm[];
    unsigned int*  s_sup   = (unsigned int*)(sm + KB_SUP);
    float*         s_x1    = (float*)(sm + KB_X1);
    float*         s_y1    = (float*)(sm + KB_Y1);
    float*         s_x2    = (float*)(sm + KB_X2);
    float*         s_y2    = (float*)(sm + KB_Y2);
    float*         s_sc    = (float*)(sm + KB_SC);
    unsigned int*  s_raw   = (unsigned int*)(sm + KB_RAW);
    unsigned int*  s_validw= (unsigned int*)(sm + KB_VALW);
    unsigned int*  s_keepw = (unsigned int*)(sm + KB_KEEPW);

    const int b    = blockIdx.x;
    const int tid  = threadIdx.x;
    const int lane = tid & 31;
    const unsigned FULL = 0xffffffffu;

    // stage sup matrix: coalesced LDG (w-major) -> padded SMEM rows
    const unsigned int* supb = g_sup + (size_t)b * WORDS * KC;
    for (int t = tid; t < WORDS * KC; t += NT) {
        int w = t >> 10;
        int i = t & 1023;
        s_sup[i * PAD + w] = supb[t];
    }
    for (int t = tid; t < KC; t += NT) {
        size_t o = (size_t)b * KC + t;
        s_x1[t] = g_bx1[o]; s_y1[t] = g_by1[o];
        s_x2[t] = g_bx2[o]; s_y2[t] = g_by2[o];
        float sc = __uint_as_float((unsigned int)(g_keys[o] >> 32));
        s_sc[t] = sc;
        unsigned int bal = __ballot_sync(FULL, sc > 0.5f);
        if (lane == 0) s_validw[t >> 5] = bal;
    }
    if (tid < 32) {
        unsigned int ra = 0;
        #pragma unroll
        for (int sl = 0; sl < SLICES; sl++)
            ra |= g_rowany[((b * SLICES + sl) << 5) + tid];
        s_raw[tid] = ra;
    }
    __syncthreads();

    // greedy scan: one warp, suppressors-only loop, no shfl in chain
    if (tid < 32) {
        unsigned int remv = 0;   // lane holds removed-mask word `lane`
        for (int w = 0; w < 32; w++) {
            unsigned int rm = __shfl_sync(FULL, remv, w);  // once per word
            unsigned int vw = s_validw[w];
            unsigned int ra = s_raw[w];
            unsigned int kw = 0;
            unsigned int pending = vw & ra;
            unsigned int scand;
            while ((scand = pending & ~rm) != 0) {
                int bit = __ffs(scand) - 1;
                pending &= ~(1u << bit);
                kw |= (1u << bit);
                int i = (w << 5) + bit;
                unsigned int rowl = s_sup[i * PAD + lane];  // per-lane word
                unsigned int roww = s_sup[i * PAD + w];     // broadcast
                remv |= rowl;
                rm   |= roww;
            }
            kw |= vw & ~ra & ~rm;  // non-suppressors kept iff never removed
            if (lane == 0) s_keepw[w] = kw;
        }
    }
    __syncthreads();

    // outputs: dets [B,KC,5], keep [B,KC]
    const bool write_keep = (out_size >= BB * KC * 6);
    for (int t = tid; t < KC; t += NT) {
        bool kept = (s_keepw[t >> 5] >> (t & 31)) & 1u;
        float kf = kept ? 1.0f : 0.0f;
        size_t base = ((size_t)b * KC + t) * 5;
        out[base + 0] = __fmul_rn(s_x1[t], kf);
        out[base + 1] = __fmul_rn(s_y1[t], kf);
        out[base + 2] = __fmul_rn(s_x2[t], kf);
        out[base + 3] = __fmul_rn(s_y2[t], kf);
        out[base + 4] = __fmul_rn(s_sc[t], kf);
        if (write_keep)
            out[(size_t)BB * KC * 5 + (size_t)b * KC + t] = kf;
    }
}

// ======================= launch ==============================================
extern "C" void kernel_launch(void* const* d_in, const int* in_sizes, int n_in,
                              void* d_out, int out_size)
{
    (void)in_sizes; (void)n_in;
    cudaFuncSetAttribute(kA_select,
        cudaFuncAttributeMaxDynamicSharedMemorySize, KA_TOTAL);
    cudaFuncSetAttribute(kB_scan,
        cudaFuncAttributeMaxDynamicSharedMemorySize, KB_TOTAL);
    const float* locs   = (const float*)d_in[0];
    const float* confs  = (const float*)d_in[1];
    const float* priors = (const float*)d_in[2];
    float* out = (float*)d_out;

    kA_select<<<BB, NT, KA_TOTAL>>>(locs, confs, priors);
    kS_supmat<<<dim3(SLICES, BB), NT>>>();
    kB_scan<<<BB, NT, KB_TOTAL>>>(out, out_size);
}